// round 9
// baseline (speedup 1.0000x reference)
#include <cuda_runtime.h>
#include <cuda_bf16.h>
#include <cstdint>

// Dilate (zero-insertion upsample) with stride (2,2):
//   in : (16, 64, 256, 256) fp32
//   out: (16, 64, 512, 512) fp32, out[b,c,2i,2j] = in[b,c,i,j], rest 0.
//
// R5 structure (measured optimum: one 2KB output row per warp, warp-uniform
// parity branch, 256 thr/block, streaming hints) + sm_100 256-bit stores:
// each st.global.v8.f32 writes 32B/lane -> 1024B contiguous per warp burst,
// halving store instructions / L1 wavefronts vs 128-bit stores.
// Per lane: even rows = 2x 16B loads + 2x 32B v8 stores; odd rows = 2x v8
// zero stores. Traffic: 268MB read + 1.074GB write = the exact floor.

#ifndef DIL_THREADS
#define DIL_THREADS 256
#endif

__device__ __forceinline__ void stg_cs_v8(float* p,
                                          float a0, float a1, float a2, float a3,
                                          float a4, float a5, float a6, float a7)
{
    asm volatile(
        "st.global.cs.v8.f32 [%0], {%1,%2,%3,%4,%5,%6,%7,%8};"
        :: "l"(p), "f"(a0), "f"(a1), "f"(a2), "f"(a3),
                   "f"(a4), "f"(a5), "f"(a6), "f"(a7)
        : "memory");
}

__global__ void __launch_bounds__(DIL_THREADS)
Dilate_35708358099161_kernel(const float4* __restrict__ in4,
                             float* __restrict__ out)
{
    unsigned int tid  = blockIdx.x * DIL_THREADS + threadIdx.x;
    unsigned int row  = tid >> 5;        // global output row, one per warp
    unsigned int lane = tid & 31u;

    unsigned int h = row & 511u;         // out row within image

    // lane's first 32B chunk of the row: float index = row*512 + lane*8
    // warp per instruction covers 32*32B = 1024B contiguous
    float* p0 = out + ((size_t)row << 9) + ((size_t)lane << 3);
    float* p1 = p0 + 256;                // second half of the 2KB row

    if (h & 1u) {
        stg_cs_v8(p0, 0.f,0.f,0.f,0.f, 0.f,0.f,0.f,0.f);
        stg_cs_v8(p1, 0.f,0.f,0.f,0.f, 0.f,0.f,0.f,0.f);
    } else {
        unsigned int bc   = row >> 9;    // image index, 0..1023
        unsigned int hin  = h >> 1;      // input row, 0..255
        // input float4 base: bc*256*64 + hin*64 + lane
        unsigned int base = (bc << 14) + (hin << 6) + lane;

        // two independent 512B-coalesced 16B loads (full 1KB input row/warp)
        float4 a = __ldcs(&in4[base]);
        float4 b = __ldcs(&in4[base + 32]);

        stg_cs_v8(p0, a.x, 0.f, a.y, 0.f, a.z, 0.f, a.w, 0.f);
        stg_cs_v8(p1, b.x, 0.f, b.y, 0.f, b.z, 0.f, b.w, 0.f);
    }
}

extern "C" void kernel_launch(void* const* d_in, const int* in_sizes, int n_in,
                              void* d_out, int out_size)
{
    const float4* in4 = (const float4*)d_in[0];
    float* out = (float*)d_out;

    // out rows = out_size / 512 = 524,288; one warp per row
    const unsigned int nthreads = (unsigned int)(out_size / 16);
    const unsigned int blocks = nthreads / DIL_THREADS;  // exact: 65,536

    Dilate_35708358099161_kernel<<<blocks, DIL_THREADS>>>(in4, out);
}

// round 10
// speedup vs baseline: 1.0148x; 1.0148x over previous
#include <cuda_runtime.h>
#include <cuda_bf16.h>

// Dilate (zero-insertion upsample) with stride (2,2):
//   in : (16, 64, 256, 256) fp32
//   out: (16, 64, 512, 512) fp32, out[b,c,2i,2j] = in[b,c,i,j], rest 0.
//
// FINAL — measured-optimal configuration across 9 rounds:
//   - one output row (2KB = 128 float4) per WARP; lane handles float4
//     offsets lane + {0,32,64,96} -> four warp-contiguous 512B stores
//     (R2 showed strided stores cost 6%)
//   - warp-uniform parity branch kept (R6 branch-free variant was slower)
//   - four front-batched 256B-coalesced loads, MLP=4 (R1->R3->R5 monotone)
//   - 256 threads/block (R7: 512 saturates per-SM L1tex queue, -10%)
//   - streaming cache hints (read-once / write-once)
//   - 256-bit stores tested (R9): no effect; warp-level burst already maximal
// Traffic: 268MB read + 1.074GB write = the exact floor.
// Achieved: ~6.6-6.7 TB/s (83-84% of 8TB/s spec) = the chip's 1:4 R:W
// mixed-stream DRAM ceiling; residual is bus-turnaround/protocol overhead.

#ifndef DIL_THREADS
#define DIL_THREADS 256
#endif

__global__ void __launch_bounds__(DIL_THREADS)
Dilate_35708358099161_kernel(const float2* __restrict__ in2,
                             float4* __restrict__ out4)
{
    unsigned int tid  = blockIdx.x * DIL_THREADS + threadIdx.x;
    unsigned int row  = tid >> 5;        // global output row, one per warp
    unsigned int lane = tid & 31u;

    unsigned int h = row & 511u;         // out row within image
    unsigned int v = (row << 7) + lane;  // first float4 index for this lane

    const float4 z = make_float4(0.f, 0.f, 0.f, 0.f);

    if (h & 1u) {
        __stcs(&out4[v],       z);
        __stcs(&out4[v + 32],  z);
        __stcs(&out4[v + 64],  z);
        __stcs(&out4[v + 96],  z);
    } else {
        unsigned int bc   = row >> 9;    // image index, 0..1023
        unsigned int hin  = h >> 1;      // input row, 0..255
        unsigned int base = (bc << 15) + (hin << 7) + lane;  // float2 units

        // four independent 256B-coalesced loads (full 1KB input row per warp)
        float2 a = __ldcs(&in2[base]);
        float2 b = __ldcs(&in2[base + 32]);
        float2 c = __ldcs(&in2[base + 64]);
        float2 d = __ldcs(&in2[base + 96]);

        __stcs(&out4[v],      make_float4(a.x, 0.f, a.y, 0.f));
        __stcs(&out4[v + 32], make_float4(b.x, 0.f, b.y, 0.f));
        __stcs(&out4[v + 64], make_float4(c.x, 0.f, c.y, 0.f));
        __stcs(&out4[v + 96], make_float4(d.x, 0.f, d.y, 0.f));
    }
}

extern "C" void kernel_launch(void* const* d_in, const int* in_sizes, int n_in,
                              void* d_out, int out_size)
{
    const float2* in2 = (const float2*)d_in[0];
    float4* out4 = (float4*)d_out;

    // out rows = out_size / 512 = 524,288; one warp per row
    const unsigned int nthreads = (unsigned int)(out_size / 16);
    const unsigned int blocks = nthreads / DIL_THREADS;  // exact: 65,536

    Dilate_35708358099161_kernel<<<blocks, DIL_THREADS>>>(in2, out4);
}